// round 2
// baseline (speedup 1.0000x reference)
#include <cuda_runtime.h>
#include <math.h>
#include <float.h>

#define NU 40000
#define NP 20000
#define DD 128
#define NE 500000
#define NB 256
#define NPOSI 100
#define KTOP 20

// ---------------- device scratch (static, no allocation) ----------------
__device__ __align__(16) float g_su[3 * NU * DD];    // running user sums per behavior
__device__ __align__(16) float g_sp[3 * NP * DD];    // running poi sums per behavior
__device__ __align__(16) float g_ub[3 * NU * DD];    // raw u per behavior
__device__ __align__(16) float g_pb[3 * NP * DD];    // raw p per behavior
__device__ __align__(16) float g_uf[NU * DD];        // per-behavior user final linear (reused)
__device__ __align__(16) float g_idf[NU * DD];       // id_feat accumulator
__device__ __align__(16) float g_uu[NB * NU];        // similarity scores
__device__ __align__(16) float g_rb[NB * DD];        // uf[batch] @ Wp
__device__ __align__(16) float g_bs[NB * DD];        // select layer bs
__device__ __align__(16) float g_pred[NB * NPOSI];   // predict accumulator
__device__ int g_ucnt[NU];
__device__ int g_pcnt[NP];
__device__ int g_uptr[NU + 1];
__device__ int g_pptr[NP + 1];
__device__ int g_ueid[NE];
__device__ int g_peid[NE];

// ---------------- helpers ----------------
__device__ __forceinline__ float warp_sum(float v) {
    #pragma unroll
    for (int o = 16; o; o >>= 1) v += __shfl_xor_sync(0xffffffffu, v, o);
    return v;
}

__device__ __forceinline__ float softmax3(const float* __restrict__ p, int i) {
    float a = p[0], b = p[1], c = p[2];
    float m = fmaxf(a, fmaxf(b, c));
    float ea = expf(a - m), eb = expf(b - m), ec = expf(c - m);
    float s = ea + eb + ec;
    float v = (i == 0) ? ea : ((i == 1) ? eb : ec);
    return v / s;
}

__device__ __forceinline__ void fma4(float4& a, float v, const float4& x) {
    a.x = fmaf(v, x.x, a.x); a.y = fmaf(v, x.y, a.y);
    a.z = fmaf(v, x.z, a.z); a.w = fmaf(v, x.w, a.w);
}

// ---------------- CSR build ----------------
__global__ void k_zero() {
    int i = blockIdx.x * blockDim.x + threadIdx.x;
    if (i < NU) g_ucnt[i] = 0;
    if (i < NP) g_pcnt[i] = 0;
    if (i < NB * NPOSI) g_pred[i] = 0.f;
}

__global__ void k_hist(const int* __restrict__ er, const int* __restrict__ ec) {
    int e = blockIdx.x * blockDim.x + threadIdx.x;
    if (e < NE) {
        atomicAdd(&g_ucnt[er[e]], 1);
        atomicAdd(&g_pcnt[ec[e]], 1);
    }
}

__global__ void k_scan(int* __restrict__ cnt, int* __restrict__ ptr, int n) {
    __shared__ int part[1024];
    int t = threadIdx.x;
    int chunk = (n + 1023) >> 10;
    int lo = t * chunk; if (lo > n) lo = n;
    int hi = lo + chunk; if (hi > n) hi = n;
    int s = 0;
    for (int i = lo; i < hi; i++) s += cnt[i];
    part[t] = s;
    __syncthreads();
    for (int off = 1; off < 1024; off <<= 1) {
        int v = (t >= off) ? part[t - off] : 0;
        __syncthreads();
        part[t] += v;
        __syncthreads();
    }
    int run = part[t] - s;  // exclusive prefix of this thread's chunk
    for (int i = lo; i < hi; i++) {
        int c = cnt[i];
        ptr[i] = run;
        run += c;
        cnt[i] = 0;  // reuse as fill counter
    }
    if (hi == n && lo < n) ptr[n] = run;
}

__global__ void k_scatter(const int* __restrict__ er, const int* __restrict__ ec) {
    int e = blockIdx.x * blockDim.x + threadIdx.x;
    if (e < NE) {
        int r = er[e];
        int pos = g_uptr[r] + atomicAdd(&g_ucnt[r], 1);
        g_ueid[pos] = e;
        int c = ec[e];
        int pp = g_pptr[c] + atomicAdd(&g_pcnt[c], 1);
        g_peid[pp] = e;
    }
}

// ---------------- fused 3-behavior SpMM + row-norm accumulate ----------------
// out_raw_b[r] = sum_e val_b[e] * src_b[other[e]];  out_sum_b[r] = (first? base[r] : out_sum_b[r]) + raw/||raw||
__global__ __launch_bounds__(256) void k_spmm3(
    const int* __restrict__ ptr, const int* __restrict__ eids, const int* __restrict__ other,
    const float* __restrict__ vc, const float* __restrict__ vf, const float* __restrict__ vx,
    const float* __restrict__ s0, const float* __restrict__ s1, const float* __restrict__ s2, int same,
    const float* __restrict__ base,
    float* __restrict__ r0, float* __restrict__ r1, float* __restrict__ r2,
    float* __restrict__ m0, float* __restrict__ m1, float* __restrict__ m2,
    int first, int nrows)
{
    int w = (blockIdx.x * blockDim.x + threadIdx.x) >> 5;
    int lane = threadIdx.x & 31;
    if (w >= nrows) return;
    int s = ptr[w], e = ptr[w + 1];
    float4 a0 = {0.f, 0.f, 0.f, 0.f}, a1 = a0, a2 = a0;
    for (int i = s; i < e; i++) {
        int ed = eids[i];
        int c = other[ed];
        float wc = vc[ed];
        float wf = vf[ed] + 1e-18f * wc;
        float wx = vx[ed] + 1e-18f * wc;
        float4 x0 = reinterpret_cast<const float4*>(s0 + (size_t)c * DD)[lane];
        float4 x1, x2;
        if (same) { x1 = x0; x2 = x0; }
        else {
            x1 = reinterpret_cast<const float4*>(s1 + (size_t)c * DD)[lane];
            x2 = reinterpret_cast<const float4*>(s2 + (size_t)c * DD)[lane];
        }
        fma4(a0, wc, x0);
        fma4(a1, wf, x1);
        fma4(a2, wx, x2);
    }
    float n0 = warp_sum(a0.x * a0.x + a0.y * a0.y + a0.z * a0.z + a0.w * a0.w);
    float n1 = warp_sum(a1.x * a1.x + a1.y * a1.y + a1.z * a1.z + a1.w * a1.w);
    float n2 = warp_sum(a2.x * a2.x + a2.y * a2.y + a2.z * a2.z + a2.w * a2.w);
    float i0 = 1.f / sqrtf(n0);
    float i1 = 1.f / sqrtf(n1);
    float i2 = 1.f / sqrtf(n2);
    size_t off = (size_t)w * DD;
    reinterpret_cast<float4*>(r0 + off)[lane] = a0;
    reinterpret_cast<float4*>(r1 + off)[lane] = a1;
    reinterpret_cast<float4*>(r2 + off)[lane] = a2;
    float4 bse = {0.f, 0.f, 0.f, 0.f};
    if (first) bse = reinterpret_cast<const float4*>(base + off)[lane];
    float4 o0 = first ? bse : reinterpret_cast<const float4*>(m0 + off)[lane];
    float4 o1 = first ? bse : reinterpret_cast<const float4*>(m1 + off)[lane];
    float4 o2 = first ? bse : reinterpret_cast<const float4*>(m2 + off)[lane];
    fma4(o0, i0, a0);
    fma4(o1, i1, a1);
    fma4(o2, i2, a2);
    reinterpret_cast<float4*>(m0 + off)[lane] = o0;
    reinterpret_cast<float4*>(m1 + off)[lane] = o1;
    reinterpret_cast<float4*>(m2 + off)[lane] = o2;
}

// ---------------- generic fp32 GEMM: C[M,N] = Agather[M,128] x B (optional transpose) ----------------
// transB=1: C[m,n] = sum_k A[m,k] * B[n,k];  transB=0: C[m,n] = sum_k A[m,k] * B[k,n]
// optional: row gather on A, bias add, accumulate alpha*C into accOut (alpha = softmax(fw)[fidx])
__global__ __launch_bounds__(256) void k_gemm(
    const float* __restrict__ A, const int* __restrict__ aidx,
    const float* __restrict__ B, int transB,
    float* __restrict__ C, int N,
    const float* __restrict__ bias,
    float* __restrict__ accOut, const float* __restrict__ fw, int fidx, int accInit)
{
    __shared__ float As[32][68];
    __shared__ float Bs[32][68];
    int m0 = blockIdx.y * 64, n0 = blockIdx.x * 64;
    int t = threadIdx.x;
    int tx = t & 15, ty = t >> 4;
    float acc[4][4] = {};
    for (int kc = 0; kc < 4; kc++) {
        #pragma unroll
        for (int i = 0; i < 8; i++) {
            int idx = t + i * 256;
            int kk = idx & 31, mm = idx >> 5;
            int row = m0 + mm;
            if (aidx) row = aidx[row];
            As[kk][mm] = A[(size_t)row * DD + kc * 32 + kk];
        }
        #pragma unroll
        for (int i = 0; i < 8; i++) {
            int idx = t + i * 256;
            if (transB) {
                int kk = idx & 31, nn = idx >> 5;
                Bs[kk][nn] = B[(size_t)(n0 + nn) * DD + kc * 32 + kk];
            } else {
                int nn = idx & 63, kk = idx >> 6;
                Bs[kk][nn] = B[(size_t)(kc * 32 + kk) * DD + n0 + nn];
            }
        }
        __syncthreads();
        #pragma unroll
        for (int kk = 0; kk < 32; kk++) {
            float4 av = *reinterpret_cast<const float4*>(&As[kk][ty * 4]);
            float4 bv = *reinterpret_cast<const float4*>(&Bs[kk][tx * 4]);
            float am[4] = {av.x, av.y, av.z, av.w};
            float bm[4] = {bv.x, bv.y, bv.z, bv.w};
            #pragma unroll
            for (int i = 0; i < 4; i++)
                #pragma unroll
                for (int j = 0; j < 4; j++)
                    acc[i][j] = fmaf(am[i], bm[j], acc[i][j]);
        }
        __syncthreads();
    }
    float alpha = 0.f;
    if (accOut) alpha = softmax3(fw, fidx);
    #pragma unroll
    for (int i = 0; i < 4; i++) {
        int row = m0 + ty * 4 + i;
        #pragma unroll
        for (int j = 0; j < 4; j++) {
            int col = n0 + tx * 4 + j;
            float v = acc[i][j];
            if (bias) v += bias[col];
            C[(size_t)row * N + col] = v;
            if (accOut) {
                float prev = accInit ? 0.f : accOut[(size_t)row * N + col];
                accOut[(size_t)row * N + col] = prev + alpha * v;
            }
        }
    }
}

// ---------------- predict accumulation: pred[b,j] += wn * dot(rb[b], sp[poi[b,j]]) ----------------
__global__ void k_pred(const float* __restrict__ rb, const float* __restrict__ sp,
                       const int* __restrict__ poi_index, const float* __restrict__ w, int widx)
{
    int gw = (blockIdx.x * blockDim.x + threadIdx.x) >> 5;
    int lane = threadIdx.x & 31;
    if (gw >= NB * NPOSI) return;
    int b = gw / NPOSI;
    int p = poi_index[gw];
    float4 rv = reinterpret_cast<const float4*>(rb + (size_t)b * DD)[lane];
    float4 sv = reinterpret_cast<const float4*>(sp + (size_t)p * DD)[lane];
    float dot = rv.x * sv.x + rv.y * sv.y + rv.z * sv.z + rv.w * sv.w;
    dot = warp_sum(dot);
    if (lane == 0) {
        float wn = softmax3(w, widx);
        g_pred[gw] += wn * dot;
    }
}

// ---------------- BCE loss (mean) ----------------
__global__ void k_loss(const float* __restrict__ labels, float* __restrict__ out) {
    __shared__ float red[1024];
    int t = threadIdx.x;
    float s = 0.f;
    for (int i = t; i < NB * NPOSI; i += 1024) {
        float x = g_pred[i], y = labels[i];
        s += fmaxf(x, 0.f) - x * y + log1pf(expf(-fabsf(x)));
    }
    red[t] = s;
    __syncthreads();
    for (int o = 512; o; o >>= 1) {
        if (t < o) red[t] += red[t + o];
        __syncthreads();
    }
    if (t == 0) out[0] = red[0] / (float)(NB * NPOSI);
}

// ---------------- top-20 + softmax + weighted gather of global_user_feature ----------------
__global__ __launch_bounds__(256) void k_topk(const float* __restrict__ guf, float* __restrict__ out) {
    __shared__ float sv[256 * KTOP];
    __shared__ int si[256 * KTOP];
    __shared__ float rv[256];
    __shared__ int ri[256];
    __shared__ float topv[KTOP];
    __shared__ int topi[KTOP];
    __shared__ float probs[KTOP];
    int b = blockIdx.x, t = threadIdx.x;
    const float* row = g_uu + (size_t)b * NU;
    float lv[KTOP];
    int li[KTOP];
    #pragma unroll
    for (int k = 0; k < KTOP; k++) { lv[k] = -FLT_MAX; li[k] = 0x7fffffff; }
    for (int u = t; u < NU; u += 256) {
        float v = row[u];
        if (v > lv[KTOP - 1]) {
            int j = KTOP - 1;
            while (j > 0 && v > lv[j - 1]) { lv[j] = lv[j - 1]; li[j] = li[j - 1]; j--; }
            lv[j] = v; li[j] = u;
        }
    }
    for (int k = 0; k < KTOP; k++) { sv[t * KTOP + k] = lv[k]; si[t * KTOP + k] = li[k]; }
    __syncthreads();
    for (int k = 0; k < KTOP; k++) {
        float bv = -FLT_MAX;
        int bi = 0x7fffffff;
        for (int s_ = 0; s_ < KTOP; s_++) {
            float v = sv[t * KTOP + s_];
            int ii = si[t * KTOP + s_];
            if (v > bv || (v == bv && ii < bi)) { bv = v; bi = ii; }
        }
        rv[t] = bv; ri[t] = bi;
        __syncthreads();
        for (int o = 128; o; o >>= 1) {
            if (t < o) {
                float v2 = rv[t + o];
                int i2 = ri[t + o];
                if (v2 > rv[t] || (v2 == rv[t] && i2 < ri[t])) { rv[t] = v2; ri[t] = i2; }
            }
            __syncthreads();
        }
        if (t == 0) { topv[k] = rv[0]; topi[k] = ri[0]; }
        __syncthreads();
        int wi = topi[k];
        for (int s_ = 0; s_ < KTOP; s_++)
            if (si[t * KTOP + s_] == wi) sv[t * KTOP + s_] = -FLT_MAX;
        __syncthreads();
    }
    if (t == 0) {
        float mx = topv[0];
        float sum = 0.f;
        for (int k = 0; k < KTOP; k++) { float e = expf(topv[k] - mx); probs[k] = e; sum += e; }
        for (int k = 0; k < KTOP; k++) probs[k] /= sum;
    }
    __syncthreads();
    if (t < DD) {
        float a = 0.f;
        for (int k = 0; k < KTOP; k++)
            a = fmaf(probs[k], guf[(size_t)topi[k] * DD + t], a);
        out[1 + (size_t)b * DD + t] = a;
    }
}

// ---------------- launch ----------------
extern "C" void kernel_launch(void* const* d_in, const int* in_sizes, int n_in,
                              void* d_out, int out_size) {
    const int*   edge_row = (const int*)d_in[0];
    const int*   edge_col = (const int*)d_in[1];
    const float* click    = (const float*)d_in[2];
    const float* favor    = (const float*)d_in[3];
    const float* consume  = (const float*)d_in[4];
    const float* uid      = (const float*)d_in[5];
    const float* pid      = (const float*)d_in[6];
    const int*   user_idx = (const int*)d_in[7];
    const int*   poi_idx  = (const int*)d_in[8];
    const float* labels   = (const float*)d_in[9];
    const float* guf      = (const float*)d_in[10];
    const float* w        = (const float*)d_in[11];
    const float* fw       = (const float*)d_in[12];
    const float* Wu[3]    = {(const float*)d_in[13], (const float*)d_in[15], (const float*)d_in[17]};
    const float* Wp[3]    = {(const float*)d_in[14], (const float*)d_in[16], (const float*)d_in[18]};
    const float* Ws       = (const float*)d_in[19];
    const float* bsb      = (const float*)d_in[20];
    float* out = (float*)d_out;

    // behavior order: 0=click, 1=favor, 2=consume
    const int widx[3] = {1, 0, 2};  // alt weights: favor->wn0, click->wn1, consume->wn2
    const int fidx[3] = {2, 0, 1};  // id_feat weights: favor->fw0, consume->fw1, click->fw2

    float *su, *sp, *ub, *pb, *uf, *idf, *uu, *rb, *bs;
    int *ucnt, *pcnt, *uptr, *pptr, *ueid, *peid;
    cudaGetSymbolAddress((void**)&su, g_su);
    cudaGetSymbolAddress((void**)&sp, g_sp);
    cudaGetSymbolAddress((void**)&ub, g_ub);
    cudaGetSymbolAddress((void**)&pb, g_pb);
    cudaGetSymbolAddress((void**)&uf, g_uf);
    cudaGetSymbolAddress((void**)&idf, g_idf);
    cudaGetSymbolAddress((void**)&uu, g_uu);
    cudaGetSymbolAddress((void**)&rb, g_rb);
    cudaGetSymbolAddress((void**)&bs, g_bs);
    cudaGetSymbolAddress((void**)&ucnt, g_ucnt);
    cudaGetSymbolAddress((void**)&pcnt, g_pcnt);
    cudaGetSymbolAddress((void**)&uptr, g_uptr);
    cudaGetSymbolAddress((void**)&pptr, g_pptr);
    cudaGetSymbolAddress((void**)&ueid, g_ueid);
    cudaGetSymbolAddress((void**)&peid, g_peid);

    const size_t SU = (size_t)NU * DD;
    const size_t SP = (size_t)NP * DD;

    // 1) CSR build
    k_zero<<<(NU + 255) / 256, 256>>>();
    k_hist<<<(NE + 255) / 256, 256>>>(edge_row, edge_col);
    k_scan<<<1, 1024>>>(ucnt, uptr, NU);
    k_scan<<<1, 1024>>>(pcnt, pptr, NP);
    k_scatter<<<(NE + 255) / 256, 256>>>(edge_row, edge_col);

    // 2) fused GCN propagation (3 behaviors together), 2 layers
    int ublk = (NU * 32 + 255) / 256;
    int pblk = (NP * 32 + 255) / 256;
    // layer 1: u from pid_embed (shared src)
    k_spmm3<<<ublk, 256>>>(uptr, ueid, edge_col, click, favor, consume,
                           pid, pid, pid, 1, uid,
                           ub, ub + SU, ub + 2 * SU,
                           su, su + SU, su + 2 * SU, 1, NU);
    // layer 1: p from raw u
    k_spmm3<<<pblk, 256>>>(pptr, peid, edge_row, click, favor, consume,
                           ub, ub + SU, ub + 2 * SU, 0, pid,
                           pb, pb + SP, pb + 2 * SP,
                           sp, sp + SP, sp + 2 * SP, 1, NP);
    // layer 2: u from raw p
    k_spmm3<<<ublk, 256>>>(uptr, ueid, edge_col, click, favor, consume,
                           pb, pb + SP, pb + 2 * SP, 0, uid,
                           ub, ub + SU, ub + 2 * SU,
                           su, su + SU, su + 2 * SU, 0, NU);
    // layer 2: p from raw u
    k_spmm3<<<pblk, 256>>>(pptr, peid, edge_row, click, favor, consume,
                           ub, ub + SU, ub + 2 * SU, 0, pid,
                           pb, pb + SP, pb + 2 * SP,
                           sp, sp + SP, sp + 2 * SP, 0, NP);

    // 3) per-behavior: uf = su @ Wu^T (+ id_feat accumulate); rb = uf[batch] @ Wp; predict accumulate
    for (int b = 0; b < 3; b++) {
        k_gemm<<<dim3(DD / 64, NU / 64), 256>>>(su + (size_t)b * SU, nullptr, Wu[b], 1,
                                                uf, DD, nullptr, idf, fw, fidx[b], b == 0);
        k_gemm<<<dim3(DD / 64, NB / 64), 256>>>(uf, user_idx, Wp[b], 0,
                                                rb, DD, nullptr, nullptr, nullptr, 0, 0);
        k_pred<<<(NB * NPOSI * 32 + 255) / 256, 256>>>(rb, sp + (size_t)b * SP, poi_idx, w, widx[b]);
    }

    // 4) select layer: bs = id_feat[cur] @ Ws^T + bias;  uu = bs @ id_feat^T
    k_gemm<<<dim3(DD / 64, NB / 64), 256>>>(idf, user_idx, Ws, 1,
                                            bs, DD, bsb, nullptr, nullptr, 0, 0);
    k_gemm<<<dim3(NU / 64, NB / 64), 256>>>(bs, nullptr, idf, 1,
                                            uu, NU, nullptr, nullptr, nullptr, 0, 0);

    // 5) top-k + user_feature; BCE loss
    k_topk<<<NB, 256>>>(guf, out);
    k_loss<<<1, 1024>>>(labels, out);
}

// round 3
// speedup vs baseline: 1.0566x; 1.0566x over previous
#include <cuda_runtime.h>
#include <math.h>
#include <float.h>

#define NU 40000
#define NP 20000
#define DD 128
#define NE 500000
#define NB 256
#define NPOSI 100
#define KTOP 20

// ---------------- device scratch (static, no allocation) ----------------
__device__ __align__(16) float g_su[3 * NU * DD];    // running user sums per behavior
__device__ __align__(16) float g_sp[3 * NP * DD];    // running poi sums per behavior
__device__ __align__(16) float g_ub[3 * NU * DD];    // raw u per behavior
__device__ __align__(16) float g_pb[3 * NP * DD];    // raw p per behavior
__device__ __align__(16) float g_idf[NU * DD];       // id_feat
__device__ __align__(16) float g_uu[NB * NU];        // similarity scores
__device__ __align__(16) float g_rb[3 * NB * DD];    // su[batch] @ M_b per behavior
__device__ __align__(16) float g_bs[NB * DD];        // select layer bs
__device__ __align__(16) float g_pred[NB * NPOSI];   // predict
__device__ __align__(16) float g_wcat[DD * 3 * DD];  // [128][384] fwn-scaled Wu concat
__device__ __align__(16) float g_mb[3 * DD * DD];    // M_b = Wu_b^T @ Wp_b
__device__ __align__(16) float4 g_urec[NE];          // packed CSR edges (user rows)
__device__ __align__(16) float4 g_prec[NE];          // packed CSR edges (poi rows)
__device__ int g_ucnt[NU];
__device__ int g_pcnt[NP];
__device__ int g_uptr[NU + 1];
__device__ int g_pptr[NP + 1];

// ---------------- helpers ----------------
__device__ __forceinline__ float warp_sum(float v) {
    #pragma unroll
    for (int o = 16; o; o >>= 1) v += __shfl_xor_sync(0xffffffffu, v, o);
    return v;
}

__device__ __forceinline__ float softmax3(const float* __restrict__ p, int i) {
    float a = p[0], b = p[1], c = p[2];
    float m = fmaxf(a, fmaxf(b, c));
    float ea = expf(a - m), eb = expf(b - m), ec = expf(c - m);
    float s = ea + eb + ec;
    float v = (i == 0) ? ea : ((i == 1) ? eb : ec);
    return v / s;
}

__device__ __forceinline__ void fma4(float4& a, float v, const float4& x) {
    a.x = fmaf(v, x.x, a.x); a.y = fmaf(v, x.y, a.y);
    a.z = fmaf(v, x.z, a.z); a.w = fmaf(v, x.w, a.w);
}

// ---------------- CSR build ----------------
__global__ void k_init() {
    int i = blockIdx.x * blockDim.x + threadIdx.x;
    if (i < NU) g_ucnt[i] = 0;
    if (i < NP) g_pcnt[i] = 0;
}

__global__ void k_hist(const int* __restrict__ er, const int* __restrict__ ec) {
    int e = blockIdx.x * blockDim.x + threadIdx.x;
    if (e < NE) {
        atomicAdd(&g_ucnt[er[e]], 1);
        atomicAdd(&g_pcnt[ec[e]], 1);
    }
}

__device__ void scan_body(int* __restrict__ cnt, int* __restrict__ ptr, int n, int* part) {
    int t = threadIdx.x;
    int chunk = (n + 1023) >> 10;
    int lo = t * chunk; if (lo > n) lo = n;
    int hi = lo + chunk; if (hi > n) hi = n;
    int s = 0;
    for (int i = lo; i < hi; i++) s += cnt[i];
    part[t] = s;
    __syncthreads();
    for (int off = 1; off < 1024; off <<= 1) {
        int v = (t >= off) ? part[t - off] : 0;
        __syncthreads();
        part[t] += v;
        __syncthreads();
    }
    int run = part[t] - s;
    for (int i = lo; i < hi; i++) {
        int c = cnt[i];
        ptr[i] = run;
        run += c;
        cnt[i] = 0;  // reuse as fill counter
    }
    if (hi == n && lo < n) ptr[n] = run;
}

__global__ void k_scan2() {
    __shared__ int part[1024];
    if (blockIdx.x == 0) scan_body(g_ucnt, g_uptr, NU, part);
    else                 scan_body(g_pcnt, g_pptr, NP, part);
}

// scatter: write packed, CSR-permuted edge records for both sides
__global__ void k_scatter(const int* __restrict__ er, const int* __restrict__ ec,
                          const float* __restrict__ click, const float* __restrict__ favor,
                          const float* __restrict__ consume) {
    int e = blockIdx.x * blockDim.x + threadIdx.x;
    if (e < NE) {
        float wc = click[e];
        float wf = favor[e]   + 1e-18f * wc;
        float wx = consume[e] + 1e-18f * wc;
        int r = er[e], c = ec[e];
        int pu = g_uptr[r] + atomicAdd(&g_ucnt[r], 1);
        g_urec[pu] = make_float4(__int_as_float(c), wc, wf, wx);
        int pp = g_pptr[c] + atomicAdd(&g_pcnt[c], 1);
        g_prec[pp] = make_float4(__int_as_float(r), wc, wf, wx);
    }
}

// ---------------- fused 3-behavior SpMM + row-norm accumulate ----------------
__global__ __launch_bounds__(256) void k_spmm3(
    const int* __restrict__ ptr, const float4* __restrict__ recs,
    const float* __restrict__ s0, const float* __restrict__ s1, const float* __restrict__ s2, int same,
    const float* __restrict__ base,
    float* __restrict__ r0, float* __restrict__ r1, float* __restrict__ r2,
    float* __restrict__ m0, float* __restrict__ m1, float* __restrict__ m2,
    int first, int nrows)
{
    int w = (blockIdx.x * blockDim.x + threadIdx.x) >> 5;
    int lane = threadIdx.x & 31;
    if (w >= nrows) return;
    int s = ptr[w], e = ptr[w + 1];
    const float4* p0 = reinterpret_cast<const float4*>(s0);
    const float4* p1 = reinterpret_cast<const float4*>(s1);
    const float4* p2 = reinterpret_cast<const float4*>(s2);
    float4 a0 = {0.f, 0.f, 0.f, 0.f}, a1 = a0, a2 = a0;
    int i = s;
    for (; i + 2 <= e; i += 2) {
        float4 rA = recs[i], rB = recs[i + 1];
        int cA = __float_as_int(rA.x);
        int cB = __float_as_int(rB.x);
        float4 xA0 = p0[(size_t)cA * 32 + lane];
        float4 xB0 = p0[(size_t)cB * 32 + lane];
        float4 xA1, xA2, xB1, xB2;
        if (same) { xA1 = xA0; xA2 = xA0; xB1 = xB0; xB2 = xB0; }
        else {
            xA1 = p1[(size_t)cA * 32 + lane];
            xB1 = p1[(size_t)cB * 32 + lane];
            xA2 = p2[(size_t)cA * 32 + lane];
            xB2 = p2[(size_t)cB * 32 + lane];
        }
        fma4(a0, rA.y, xA0); fma4(a0, rB.y, xB0);
        fma4(a1, rA.z, xA1); fma4(a1, rB.z, xB1);
        fma4(a2, rA.w, xA2); fma4(a2, rB.w, xB2);
    }
    if (i < e) {
        float4 rA = recs[i];
        int cA = __float_as_int(rA.x);
        float4 xA0 = p0[(size_t)cA * 32 + lane];
        float4 xA1, xA2;
        if (same) { xA1 = xA0; xA2 = xA0; }
        else {
            xA1 = p1[(size_t)cA * 32 + lane];
            xA2 = p2[(size_t)cA * 32 + lane];
        }
        fma4(a0, rA.y, xA0);
        fma4(a1, rA.z, xA1);
        fma4(a2, rA.w, xA2);
    }
    float n0 = warp_sum(a0.x * a0.x + a0.y * a0.y + a0.z * a0.z + a0.w * a0.w);
    float n1 = warp_sum(a1.x * a1.x + a1.y * a1.y + a1.z * a1.z + a1.w * a1.w);
    float n2 = warp_sum(a2.x * a2.x + a2.y * a2.y + a2.z * a2.z + a2.w * a2.w);
    float i0 = 1.f / sqrtf(n0);
    float i1 = 1.f / sqrtf(n1);
    float i2 = 1.f / sqrtf(n2);
    size_t off = (size_t)w * 32;
    reinterpret_cast<float4*>(r0)[off + lane] = a0;
    reinterpret_cast<float4*>(r1)[off + lane] = a1;
    reinterpret_cast<float4*>(r2)[off + lane] = a2;
    float4 bse = {0.f, 0.f, 0.f, 0.f};
    if (first) bse = reinterpret_cast<const float4*>(base)[off + lane];
    float4 o0 = first ? bse : reinterpret_cast<const float4*>(m0)[off + lane];
    float4 o1 = first ? bse : reinterpret_cast<const float4*>(m1)[off + lane];
    float4 o2 = first ? bse : reinterpret_cast<const float4*>(m2)[off + lane];
    fma4(o0, i0, a0);
    fma4(o1, i1, a1);
    fma4(o2, i2, a2);
    reinterpret_cast<float4*>(m0)[off + lane] = o0;
    reinterpret_cast<float4*>(m1)[off + lane] = o1;
    reinterpret_cast<float4*>(m2)[off + lane] = o2;
}

// ---------------- tiny weight-prep kernels ----------------
// Wcat[n][b*128+k] = fwn[b] * Wu_b[n][k], behaviors ordered (favor, consume, click)
__global__ void k_wcat(const float* __restrict__ fw,
                       const float* __restrict__ Wf, const float* __restrict__ Wc,
                       const float* __restrict__ Wcl) {
    int idx = blockIdx.x * blockDim.x + threadIdx.x;
    if (idx >= DD * 3 * DD) return;
    int n = idx / (3 * DD);
    int kk = idx - n * (3 * DD);
    int b = kk >> 7, k = kk & 127;
    const float* W = (b == 0) ? Wf : ((b == 1) ? Wc : Wcl);
    g_wcat[idx] = softmax3(fw, b) * W[n * DD + k];
}

// M_z[k][n] = sum_j Wu_z[j][k] * Wp_z[j][n]  (Wu^T @ Wp)
__global__ void k_atb(const float* __restrict__ Wu0, const float* __restrict__ Wp0,
                      const float* __restrict__ Wu1, const float* __restrict__ Wp1,
                      const float* __restrict__ Wu2, const float* __restrict__ Wp2) {
    int z = blockIdx.z;
    const float* Wu = (z == 0) ? Wu0 : ((z == 1) ? Wu1 : Wu2);
    const float* Wp = (z == 0) ? Wp0 : ((z == 1) ? Wp1 : Wp2);
    int idx = blockIdx.x * blockDim.x + threadIdx.x;
    int kI = idx >> 7, n = idx & 127;
    float acc = 0.f;
    #pragma unroll 4
    for (int j = 0; j < DD; j++)
        acc = fmaf(Wu[j * DD + kI], Wp[j * DD + n], acc);
    g_mb[z * DD * DD + kI * DD + n] = acc;
}

// rb_z[m][n] = sum_k su_z[uidx[m]][k] * M_z[k][n]
__global__ void k_rb(const int* __restrict__ uidx) {
    int z = blockIdx.z;
    const float* su = g_su + (size_t)z * NU * DD;
    const float* M = g_mb + z * DD * DD;
    int idx = blockIdx.x * blockDim.x + threadIdx.x;
    int m = idx >> 7, n = idx & 127;
    int row = uidx[m];
    float acc = 0.f;
    #pragma unroll 4
    for (int k = 0; k < DD; k++)
        acc = fmaf(su[(size_t)row * DD + k], M[k * DD + n], acc);
    g_rb[(size_t)z * NB * DD + (size_t)m * DD + n] = acc;
}

// ---------------- idf = su_cat[NU,384] @ Wcat^T (tiled) ----------------
__global__ __launch_bounds__(256) void k_idf() {
    __shared__ float As[32][68];
    __shared__ float Bs[32][68];
    int m0 = blockIdx.y * 64, n0 = blockIdx.x * 64;
    int t = threadIdx.x;
    int tx = t & 15, ty = t >> 4;
    float acc[4][4] = {};
    const size_t SU = (size_t)NU * DD;
    const float* Ab[3] = {g_su + SU, g_su + 2 * SU, g_su};  // favor, consume, click
    for (int kc = 0; kc < 12; kc++) {
        const float* A = Ab[kc >> 2];
        int k0 = (kc & 3) * 32;
        #pragma unroll
        for (int i = 0; i < 8; i++) {
            int idx = t + i * 256;
            int kk = idx & 31, mm = idx >> 5;
            As[kk][mm] = A[(size_t)(m0 + mm) * DD + k0 + kk];
        }
        #pragma unroll
        for (int i = 0; i < 8; i++) {
            int idx = t + i * 256;
            int kk = idx & 31, nn = idx >> 5;
            Bs[kk][nn] = g_wcat[(size_t)(n0 + nn) * (3 * DD) + kc * 32 + kk];
        }
        __syncthreads();
        #pragma unroll
        for (int kk = 0; kk < 32; kk++) {
            float4 av = *reinterpret_cast<const float4*>(&As[kk][ty * 4]);
            float4 bv = *reinterpret_cast<const float4*>(&Bs[kk][tx * 4]);
            float am[4] = {av.x, av.y, av.z, av.w};
            float bm[4] = {bv.x, bv.y, bv.z, bv.w};
            #pragma unroll
            for (int i = 0; i < 4; i++)
                #pragma unroll
                for (int j = 0; j < 4; j++)
                    acc[i][j] = fmaf(am[i], bm[j], acc[i][j]);
        }
        __syncthreads();
    }
    #pragma unroll
    for (int i = 0; i < 4; i++) {
        int row = m0 + ty * 4 + i;
        float4 v = {acc[i][0], acc[i][1], acc[i][2], acc[i][3]};
        *reinterpret_cast<float4*>(&g_idf[(size_t)row * DD + n0 + tx * 4]) = v;
    }
}

// ---------------- generic tiled GEMM (K=128): C = Agather @ B(^T) (+bias) ----------------
__global__ __launch_bounds__(256) void k_gemm(
    const float* __restrict__ A, const int* __restrict__ aidx,
    const float* __restrict__ B, int transB,
    float* __restrict__ C, int N, const float* __restrict__ bias)
{
    __shared__ float As[32][68];
    __shared__ float Bs[32][68];
    int m0 = blockIdx.y * 64, n0 = blockIdx.x * 64;
    int t = threadIdx.x;
    int tx = t & 15, ty = t >> 4;
    float acc[4][4] = {};
    for (int kc = 0; kc < 4; kc++) {
        #pragma unroll
        for (int i = 0; i < 8; i++) {
            int idx = t + i * 256;
            int kk = idx & 31, mm = idx >> 5;
            int row = m0 + mm;
            if (aidx) row = aidx[row];
            As[kk][mm] = A[(size_t)row * DD + kc * 32 + kk];
        }
        #pragma unroll
        for (int i = 0; i < 8; i++) {
            int idx = t + i * 256;
            if (transB) {
                int kk = idx & 31, nn = idx >> 5;
                Bs[kk][nn] = B[(size_t)(n0 + nn) * DD + kc * 32 + kk];
            } else {
                int nn = idx & 63, kk = idx >> 6;
                Bs[kk][nn] = B[(size_t)(kc * 32 + kk) * DD + n0 + nn];
            }
        }
        __syncthreads();
        #pragma unroll
        for (int kk = 0; kk < 32; kk++) {
            float4 av = *reinterpret_cast<const float4*>(&As[kk][ty * 4]);
            float4 bv = *reinterpret_cast<const float4*>(&Bs[kk][tx * 4]);
            float am[4] = {av.x, av.y, av.z, av.w};
            float bm[4] = {bv.x, bv.y, bv.z, bv.w};
            #pragma unroll
            for (int i = 0; i < 4; i++)
                #pragma unroll
                for (int j = 0; j < 4; j++)
                    acc[i][j] = fmaf(am[i], bm[j], acc[i][j]);
        }
        __syncthreads();
    }
    #pragma unroll
    for (int i = 0; i < 4; i++) {
        int row = m0 + ty * 4 + i;
        #pragma unroll
        for (int j = 0; j < 4; j++) {
            int col = n0 + tx * 4 + j;
            float v = acc[i][j];
            if (bias) v += bias[col];
            C[(size_t)row * N + col] = v;
        }
    }
}

// ---------------- predict: pred[b,j] = sum_z wn_z * dot(rb_z[b], sp_z[poi]) ----------------
__global__ void k_pred(const int* __restrict__ poi_index, const float* __restrict__ w) {
    int gw = (blockIdx.x * blockDim.x + threadIdx.x) >> 5;
    int lane = threadIdx.x & 31;
    if (gw >= NB * NPOSI) return;
    int b = gw / NPOSI;
    int p = poi_index[gw];
    const int widx[3] = {1, 0, 2};  // click->wn1, favor->wn0, consume->wn2
    float acc = 0.f;
    #pragma unroll
    for (int z = 0; z < 3; z++) {
        float4 rv = reinterpret_cast<const float4*>(g_rb + (size_t)z * NB * DD + (size_t)b * DD)[lane];
        float4 sv = reinterpret_cast<const float4*>(g_sp + (size_t)z * NP * DD + (size_t)p * DD)[lane];
        float dot = rv.x * sv.x + rv.y * sv.y + rv.z * sv.z + rv.w * sv.w;
        acc += softmax3(w, widx[z]) * dot;
    }
    acc = warp_sum(acc);
    if (lane == 0) g_pred[gw] = acc;
}

// ---------------- BCE loss (mean) ----------------
__global__ void k_loss(const float* __restrict__ labels, float* __restrict__ out) {
    __shared__ float red[1024];
    int t = threadIdx.x;
    float s = 0.f;
    for (int i = t; i < NB * NPOSI; i += 1024) {
        float x = g_pred[i], y = labels[i];
        s += fmaxf(x, 0.f) - x * y + log1pf(expf(-fabsf(x)));
    }
    red[t] = s;
    __syncthreads();
    for (int o = 512; o; o >>= 1) {
        if (t < o) red[t] += red[t + o];
        __syncthreads();
    }
    if (t == 0) out[0] = red[0] / (float)(NB * NPOSI);
}

// ---------------- top-20 + softmax + weighted gather ----------------
__global__ __launch_bounds__(256) void k_topk(const float* __restrict__ guf, float* __restrict__ out) {
    __shared__ float sv[256 * KTOP];
    __shared__ int si[256 * KTOP];
    __shared__ float rv[256];
    __shared__ int ri[256];
    __shared__ float topv[KTOP];
    __shared__ int topi[KTOP];
    __shared__ float probs[KTOP];
    int b = blockIdx.x, t = threadIdx.x;
    const float* row = g_uu + (size_t)b * NU;
    float lv[KTOP];
    int li[KTOP];
    #pragma unroll
    for (int k = 0; k < KTOP; k++) { lv[k] = -FLT_MAX; li[k] = 0x7fffffff; }
    for (int u = t; u < NU; u += 256) {
        float v = row[u];
        if (v > lv[KTOP - 1]) {
            int j = KTOP - 1;
            while (j > 0 && v > lv[j - 1]) { lv[j] = lv[j - 1]; li[j] = li[j - 1]; j--; }
            lv[j] = v; li[j] = u;
        }
    }
    for (int k = 0; k < KTOP; k++) { sv[t * KTOP + k] = lv[k]; si[t * KTOP + k] = li[k]; }
    __syncthreads();
    for (int k = 0; k < KTOP; k++) {
        float bv = -FLT_MAX;
        int bi = 0x7fffffff;
        for (int s_ = 0; s_ < KTOP; s_++) {
            float v = sv[t * KTOP + s_];
            int ii = si[t * KTOP + s_];
            if (v > bv || (v == bv && ii < bi)) { bv = v; bi = ii; }
        }
        rv[t] = bv; ri[t] = bi;
        __syncthreads();
        for (int o = 128; o; o >>= 1) {
            if (t < o) {
                float v2 = rv[t + o];
                int i2 = ri[t + o];
                if (v2 > rv[t] || (v2 == rv[t] && i2 < ri[t])) { rv[t] = v2; ri[t] = i2; }
            }
            __syncthreads();
        }
        if (t == 0) { topv[k] = rv[0]; topi[k] = ri[0]; }
        __syncthreads();
        int wi = topi[k];
        for (int s_ = 0; s_ < KTOP; s_++)
            if (si[t * KTOP + s_] == wi) sv[t * KTOP + s_] = -FLT_MAX;
        __syncthreads();
    }
    if (t == 0) {
        float mx = topv[0];
        float sum = 0.f;
        for (int k = 0; k < KTOP; k++) { float e = expf(topv[k] - mx); probs[k] = e; sum += e; }
        for (int k = 0; k < KTOP; k++) probs[k] /= sum;
    }
    __syncthreads();
    if (t < DD) {
        float a = 0.f;
        for (int k = 0; k < KTOP; k++)
            a = fmaf(probs[k], guf[(size_t)topi[k] * DD + t], a);
        out[1 + (size_t)b * DD + t] = a;
    }
}

// ---------------- launch ----------------
extern "C" void kernel_launch(void* const* d_in, const int* in_sizes, int n_in,
                              void* d_out, int out_size) {
    const int*   edge_row = (const int*)d_in[0];
    const int*   edge_col = (const int*)d_in[1];
    const float* click    = (const float*)d_in[2];
    const float* favor    = (const float*)d_in[3];
    const float* consume  = (const float*)d_in[4];
    const float* uid      = (const float*)d_in[5];
    const float* pid      = (const float*)d_in[6];
    const int*   user_idx = (const int*)d_in[7];
    const int*   poi_idx  = (const int*)d_in[8];
    const float* labels   = (const float*)d_in[9];
    const float* guf      = (const float*)d_in[10];
    const float* w        = (const float*)d_in[11];
    const float* fw       = (const float*)d_in[12];
    const float* Wu[3]    = {(const float*)d_in[13], (const float*)d_in[15], (const float*)d_in[17]};
    const float* Wp[3]    = {(const float*)d_in[14], (const float*)d_in[16], (const float*)d_in[18]};
    const float* Ws       = (const float*)d_in[19];
    const float* bsb      = (const float*)d_in[20];
    float* out = (float*)d_out;

    float *su, *sp, *ub, *pb, *idf, *uu, *bs;
    float4 *urec, *prec;
    int *uptr, *pptr;
    cudaGetSymbolAddress((void**)&su, g_su);
    cudaGetSymbolAddress((void**)&sp, g_sp);
    cudaGetSymbolAddress((void**)&ub, g_ub);
    cudaGetSymbolAddress((void**)&pb, g_pb);
    cudaGetSymbolAddress((void**)&idf, g_idf);
    cudaGetSymbolAddress((void**)&uu, g_uu);
    cudaGetSymbolAddress((void**)&bs, g_bs);
    cudaGetSymbolAddress((void**)&urec, g_urec);
    cudaGetSymbolAddress((void**)&prec, g_prec);
    cudaGetSymbolAddress((void**)&uptr, g_uptr);
    cudaGetSymbolAddress((void**)&pptr, g_pptr);

    const size_t SU = (size_t)NU * DD;
    const size_t SP = (size_t)NP * DD;

    // weight-only prep (independent of graph build)
    k_wcat<<<(DD * 3 * DD + 255) / 256, 256>>>(fw, Wu[1], Wu[2], Wu[0]);  // favor, consume, click
    k_atb<<<dim3(DD * DD / 256, 1, 3), 256>>>(Wu[0], Wp[0], Wu[1], Wp[1], Wu[2], Wp[2]);

    // 1) CSR build (packed, permuted edge records)
    k_init<<<(NU + 255) / 256, 256>>>();
    k_hist<<<(NE + 255) / 256, 256>>>(edge_row, edge_col);
    k_scan2<<<2, 1024>>>();
    k_scatter<<<(NE + 255) / 256, 256>>>(edge_row, edge_col, click, favor, consume);

    // 2) fused GCN propagation (3 behaviors together), 2 layers
    int ublk = (NU * 32 + 255) / 256;
    int pblk = (NP * 32 + 255) / 256;
    k_spmm3<<<ublk, 256>>>(uptr, urec, pid, pid, pid, 1, uid,
                           ub, ub + SU, ub + 2 * SU,
                           su, su + SU, su + 2 * SU, 1, NU);
    k_spmm3<<<pblk, 256>>>(pptr, prec, ub, ub + SU, ub + 2 * SU, 0, pid,
                           pb, pb + SP, pb + 2 * SP,
                           sp, sp + SP, sp + 2 * SP, 1, NP);
    k_spmm3<<<ublk, 256>>>(uptr, urec, pb, pb + SP, pb + 2 * SP, 0, uid,
                           ub, ub + SU, ub + 2 * SU,
                           su, su + SU, su + 2 * SU, 0, NU);
    k_spmm3<<<pblk, 256>>>(pptr, prec, ub, ub + SU, ub + 2 * SU, 0, pid,
                           pb, pb + SP, pb + 2 * SP,
                           sp, sp + SP, sp + 2 * SP, 0, NP);

    // 3) predict path: rb_z = su_z[batch] @ M_z, then dot with sp_z at poi indices
    k_rb<<<dim3(NB * DD / 256, 1, 3), 256>>>(user_idx);
    k_pred<<<(NB * NPOSI * 32 + 255) / 256, 256>>>(poi_idx, w);

    // 4) id_feat path: idf = su_cat @ Wcat^T; bs = idf[cur]@Ws^T+b; uu = bs@idf^T
    k_idf<<<dim3(DD / 64, NU / 64), 256>>>();
    k_gemm<<<dim3(DD / 64, NB / 64), 256>>>(idf, user_idx, Ws, 1, bs, DD, bsb);
    k_gemm<<<dim3(NU / 64, NB / 64), 256>>>(bs, nullptr, idf, 1, uu, NU, nullptr);

    // 5) top-k + user_feature; BCE loss
    k_topk<<<NB, 256>>>(guf, out);
    k_loss<<<1, 1024>>>(labels, out);
}